// round 14
// baseline (speedup 1.0000x reference)
#include <cuda_runtime.h>
#include <cuda_bf16.h>
#include <cuda_fp16.h>
#include <math.h>
#include <stdint.h>

// ---------------- problem constants ----------------
#define Bdoc 4
#define Lseq 1024
#define Ment 128
#define Rht  512
#define HID  1024
#define NH   16
#define NE   42
#define EMB  768
#define NBLK 12
#define NCLS 97
#define NPROJ 128
#define NROW (Bdoc*Rht)   // 2048
#define KBIL (EMB*64)     // 49152
#define NITER 384         // bilinear iters (K=128 each)

// ---------------- scratch ----------------
__device__ float g_ent_emb[Bdoc*NE*HID];
__device__ float g_attn_mean[Bdoc*NE*NH*Lseq];
__device__ float g_rel[NROW*HID];
__device__ float g_ht[2*NROW*EMB];                    // h then t (fp32)
__device__ float g_bias_ht[2*EMB];
// packed fp16x2 operands
__device__ uint32_t g_WbilHi[(size_t)EMB*KBIL/2];     // 75.5 MB
__device__ uint32_t g_WhtHi[2*EMB*HID];
__device__ uint32_t g_seqTHi[Bdoc*HID*Lseq/2];
__device__ uint32_t g_htaH[NROW*Lseq/2];
__device__ uint32_t g_XH[2*NROW*HID];

// ---------------- helpers ----------------
__device__ __forceinline__ uint32_t smem_u32(const void* p) {
    uint32_t a;
    asm("{ .reg .u64 t; cvta.to.shared.u64 t, %1; cvt.u32.u64 %0, t; }"
        : "=r"(a) : "l"(p));
    return a;
}
#define SWZ(o) ((o) ^ ((((uint32_t)(o))>>3)&0x70))

#define MMA16816H(d, a0,a1,a2,a3, b0,b1) \
    asm volatile("mma.sync.aligned.m16n8k16.row.col.f32.f16.f16.f32 " \
        "{%0,%1,%2,%3},{%4,%5,%6,%7},{%8,%9},{%0,%1,%2,%3};" \
        : "+f"((d)[0]), "+f"((d)[1]), "+f"((d)[2]), "+f"((d)[3]) \
        : "r"(a0), "r"(a1), "r"(a2), "r"(a3), "r"(b0), "r"(b1))

#define LDX4(r, addr) \
    asm volatile("ldmatrix.sync.aligned.m8n8.x4.shared.b16 {%0,%1,%2,%3},[%4];" \
        : "=r"((r)[0]), "=r"((r)[1]), "=r"((r)[2]), "=r"((r)[3]) : "r"(addr))

#define CPA16(dst, src) \
    asm volatile("cp.async.cg.shared.global [%0], [%1], 16;" :: "r"(dst), "l"(src))

__device__ __forceinline__ uint32_t pack_h2(float x, float y) {
    uint32_t r;   // lo = x, hi = y
    asm("cvt.rn.f16x2.f32 %0, %1, %2;" : "=r"(r) : "f"(y), "f"(x));
    return r;
}

// ---------------- K1: entity logsumexp pooling ----------------
__global__ void k_ent_emb(const float* __restrict__ ent,
                          const int* __restrict__ labels)
{
    int e = blockIdx.x, b = blockIdx.y;
    __shared__ int s_idx[Ment];
    __shared__ int s_cnt;
    int tid = threadIdx.x;
    if (tid == 0) {
        int c = 0;
        for (int i = 0; i < Ment; i++)
            if (labels[b*Ment + i] == e) s_idx[c++] = i;
        s_cnt = c;
    }
    __syncthreads();
    int cnt = s_cnt;
    const float* eb = ent + (size_t)b*Ment*HID;
    float* out = g_ent_emb + ((size_t)(b*NE + e))*HID;
    for (int d = tid; d < HID; d += blockDim.x) {
        float r;
        if (cnt == 0) {
            r = 0.f;
        } else {
            float mx = -3.4e38f, s = 0.f;
            for (int i = 0; i < cnt; i++) {
                float v = eb[(size_t)s_idx[i]*HID + d];
                if (v > mx) { s = s*expf(mx - v) + 1.f; mx = v; }
                else        { s += expf(v - mx); }
            }
            r = mx + logf(s);
        }
        out[d] = r;
    }
}

// ---------------- K2: per-entity mean attention ----------------
__global__ void k_attn_mean(const float* __restrict__ attn,
                            const int* __restrict__ labels)
{
    int e = blockIdx.x, h = blockIdx.y, b = blockIdx.z;
    __shared__ int s_idx[Ment];
    __shared__ int s_cnt;
    int tid = threadIdx.x;
    if (tid == 0) {
        int c = 0;
        for (int i = 0; i < Ment; i++)
            if (labels[b*Ment + i] == e) s_idx[c++] = i;
        s_cnt = c;
    }
    __syncthreads();
    int cnt = s_cnt;
    float inv = 1.f / (float)(cnt > 0 ? cnt : 1);
    const float* ab = attn + (((size_t)b*NH + h)*Ment)*Lseq;
    float* out = g_attn_mean + (((size_t)(b*NE + e))*NH + h)*Lseq;
    for (int l = tid; l < Lseq; l += blockDim.x) {
        float s = 0.f;
        for (int i = 0; i < cnt; i++) s += ab[(size_t)s_idx[i]*Lseq + l];
        out[l] = s * inv;
    }
}

// ---------------- K3: hta -> single fp16 ----------------
__global__ void k_hta(const int* __restrict__ hts)
{
    int r = blockIdx.x, b = blockIdx.y;
    int r2 = b*Rht + r;
    int e0 = hts[(size_t)r2*2 + 0];
    int e1 = hts[(size_t)r2*2 + 1];
    const float* a0 = g_attn_mean + ((size_t)(b*NE + e0))*NH*Lseq;
    const float* a1 = g_attn_mean + ((size_t)(b*NE + e1))*NH*Lseq;
    int tid = threadIdx.x;
    int l0 = tid*4;
    float4 acc = make_float4(0.f,0.f,0.f,0.f);
#pragma unroll
    for (int h = 0; h < NH; h++) {
        float4 x = *(const float4*)&a0[h*Lseq + l0];
        float4 y = *(const float4*)&a1[h*Lseq + l0];
        acc.x += x.x*y.x; acc.y += x.y*y.y;
        acc.z += x.z*y.z; acc.w += x.w*y.w;
    }
    acc.x *= (1.f/NH); acc.y *= (1.f/NH); acc.z *= (1.f/NH); acc.w *= (1.f/NH);
    __shared__ float red[256];
    red[tid] = acc.x + acc.y + acc.z + acc.w;
    __syncthreads();
    for (int o = 128; o > 0; o >>= 1) {
        if (tid < o) red[tid] += red[tid + o];
        __syncthreads();
    }
    float sc = 1.f / (red[0] + 1e-5f);
    size_t o = (size_t)r2*(Lseq/2) + tid*2;
    g_htaH[o]   = pack_h2(acc.x*sc, acc.y*sc);
    g_htaH[o+1] = pack_h2(acc.z*sc, acc.w*sc);
}

// ---------------- K5: gather -> single fp16 X ----------------
__global__ void k_gather(const int* __restrict__ hts)
{
    int r2 = blockIdx.x;
    int b = r2 / Rht;
    int e0 = hts[(size_t)r2*2 + 0];
    int e1 = hts[(size_t)r2*2 + 1];
    const float* emb0 = g_ent_emb + ((size_t)(b*NE + e0))*HID;
    const float* emb1 = g_ent_emb + ((size_t)(b*NE + e1))*HID;
    const float* rel  = g_rel + (size_t)r2*HID;
    for (int u = threadIdx.x; u < HID; u += 256) {
        if (u < HID/2) {
            float2 v0 = *(const float2*)&emb0[2*u];
            g_XH[(size_t)r2*HID + u] = pack_h2(v0.x, v0.y);
            float2 v1 = *(const float2*)&emb1[2*u];
            g_XH[(size_t)(NROW + r2)*HID + u] = pack_h2(v1.x, v1.y);
        } else {
            float2 rv = *(const float2*)&rel[2*u - HID];
            uint32_t p = pack_h2(rv.x, rv.y);
            g_XH[(size_t)r2*HID + u] = p;
            g_XH[(size_t)(NROW + r2)*HID + u] = p;
        }
    }
}

// ---------------- split + transpose: [z][K][N] f32 -> [z][N][K/2] fp16x2 ----
__global__ void __launch_bounds__(256)
k_splitT(const float* __restrict__ in, uint32_t* __restrict__ outHi,
         int K, int N, long sIn, long sOut)
{
    __shared__ float s[128][65];
    in    += (size_t)blockIdx.z * sIn;
    outHi += (size_t)blockIdx.z * sOut;
    int k0 = blockIdx.x*128, n0 = blockIdx.y*64;
    int tid = threadIdx.x;
#pragma unroll
    for (int u = 0; u < 8; u++) {
        int idx = tid + u*256;
        int kk = idx >> 4;
        int cc = (idx & 15) * 4;
        float4 v = *(const float4*)&in[(size_t)(k0+kk)*N + n0 + cc];
        s[kk][cc+0] = v.x; s[kk][cc+1] = v.y;
        s[kk][cc+2] = v.z; s[kk][cc+3] = v.w;
    }
    __syncthreads();
    int K2 = K >> 1;
#pragma unroll
    for (int u = 0; u < 4; u++) {
        int idx = tid + u*256;
        int nn = idx >> 4, q = idx & 15;
        uint32_t hi[4];
#pragma unroll
        for (int i = 0; i < 4; i++)
            hi[i] = pack_h2(s[q*8 + i*2][nn], s[q*8 + i*2 + 1][nn]);
        size_t o = (size_t)(n0+nn)*K2 + (k0 >> 1) + q*4;
        *(uint4*)&outHi[o] = make_uint4(hi[0], hi[1], hi[2], hi[3]);
    }
}

__global__ void k_bias2(const float* __restrict__ b0, const float* __restrict__ b1)
{
    int i = threadIdx.x + blockIdx.x*256;
    if (i < EMB) { g_bias_ht[i] = b0[i]; g_bias_ht[EMB+i] = b1[i]; }
}

// ---------------- 1-pass fp16 mma GEMM, templated N-tile (round-10) -------
template<int ACT, int NT>
__global__ void __launch_bounds__(256, 1)
k_gemm_h(const uint32_t* __restrict__ Ah, const uint32_t* __restrict__ Bh,
         const float* __restrict__ bias, float* __restrict__ C,
         int K, int N, long sA, long sB, long sC)
{
    constexpr int NFR  = NT/16;
    constexpr int BUFB = 16384 + NT*128;
    extern __shared__ char smem[];
    uint32_t sb = smem_u32(smem);
    int tid = threadIdx.x, lid = tid & 31, wid = tid >> 5;
    int row0 = blockIdx.y*128, col0 = blockIdx.x*NT;
    Ah += (size_t)blockIdx.z * sA;
    Bh += (size_t)blockIdx.z * sB;
    C  += (size_t)blockIdx.z * sC;
    const float* bz = bias ? bias + (size_t)blockIdx.z * N : nullptr;
    int K2 = K >> 1, nchunk = K >> 6;
    int wm = (wid >> 1)*32, wn = (wid & 1)*(NT/2);
    int msel = lid >> 3, r8 = lid & 7;

    float acc[2][NFR][4];
#pragma unroll
    for (int i = 0; i < 2; i++)
#pragma unroll
        for (int n = 0; n < NFR; n++)
#pragma unroll
            for (int q = 0; q < 4; q++) acc[i][n][q] = 0.f;

#define GLOADH(c) { \
    uint32_t base = sb + (uint32_t)((c)&1)*BUFB; \
    _Pragma("unroll") \
    for (int p = 0; p < 4; p++) { \
        int idx = tid + p*256; int r = idx >> 3, seg = idx & 7; \
        size_t goA = (size_t)(row0+r)*K2 + (size_t)(c)*32 + seg*4; \
        CPA16(base + SWZ((uint32_t)(r*128 + seg*16)), Ah + goA); \
    } \
    _Pragma("unroll") \
    for (int p = 0; p < NT/32; p++) { \
        int idx = tid + p*256; int r = idx >> 3, seg = idx & 7; \
        size_t goB = (size_t)(col0+r)*K2 + (size_t)(c)*32 + seg*4; \
        CPA16(base + 16384u + SWZ((uint32_t)(r*128 + seg*16)), Bh + goB); \
    } }

    GLOADH(0);
    asm volatile("cp.async.commit_group;");

#pragma unroll 1
    for (int c = 0; c < nchunk; ++c) {
        if (c + 1 < nchunk) GLOADH(c + 1);
        asm volatile("cp.async.commit_group;");
        asm volatile("cp.async.wait_group 1;");
        __syncthreads();

        uint32_t abase = sb + (uint32_t)(c & 1)*BUFB;
        uint32_t bbase = abase + 16384u;
#pragma unroll
        for (int s = 0; s < 4; ++s) {
            uint32_t ah[2][4];
#pragma unroll
            for (int i = 0; i < 2; ++i) {
                uint32_t off = SWZ((uint32_t)((wm + i*16 + (lid & 15))*128
                                              + s*32 + (lid >> 4)*16));
                LDX4(ah[i], abase + off);
            }
            uint32_t bh[2*NFR];
#pragma unroll
            for (int pq = 0; pq < NT/32; ++pq) {
                uint32_t off = SWZ((uint32_t)((wn + (pq*2 + (msel >> 1))*8 + r8)*128
                                              + s*32 + (msel & 1)*16));
                LDX4(&bh[pq*4], bbase + off);
            }
#pragma unroll
            for (int i = 0; i < 2; ++i)
#pragma unroll
                for (int n = 0; n < NFR; ++n)
                    MMA16816H(acc[i][n], ah[i][0],ah[i][1],ah[i][2],ah[i][3], bh[n*2], bh[n*2+1]);
        }
        __syncthreads();
    }
#undef GLOADH

#pragma unroll
    for (int i = 0; i < 2; ++i) {
        int gr = row0 + wm + i*16 + (lid >> 2);
#pragma unroll
        for (int n = 0; n < NFR; ++n) {
            int gc = col0 + wn + n*8 + (lid & 3)*2;
            float b0v = bz ? bz[gc] : 0.f, b1v = bz ? bz[gc+1] : 0.f;
            float v0 = acc[i][n][0] + b0v, v1 = acc[i][n][1] + b1v;
            float v2 = acc[i][n][2] + b0v, v3 = acc[i][n][3] + b1v;
            if (ACT == 1) { v0 = tanhf(v0); v1 = tanhf(v1); v2 = tanhf(v2); v3 = tanhf(v3); }
            *(float2*)&C[(size_t)gr*N + gc]     = make_float2(v0, v1);
            *(float2*)&C[(size_t)(gr+8)*N + gc] = make_float2(v2, v3);
        }
    }
}

// ---------------- fp32 SIMT sgemm (small tails: cls/proj) ----------------
template<int BM, int BN, int BK, int TM, int TN, int ACT>
__global__ __launch_bounds__((BM/TM)*(BN/TN))
void sgemm(const float* __restrict__ A, const float* __restrict__ B,
           const float* __restrict__ bias, float* __restrict__ C,
           int M, int N, int K)
{
    constexpr int THREADS = (BM/TM)*(BN/TN);
    __shared__ float As[BK][BM + 4];
    __shared__ float Bs[BK][BN];
    int tid = threadIdx.x;
    int tx = tid % (BN/TN);
    int ty = tid / (BN/TN);
    int row0 = blockIdx.y * BM, col0 = blockIdx.x * BN;
    float acc[TM][TN] = {};
    constexpr int AE = BM*BK/THREADS;
    constexpr int BE = BK*BN/THREADS;

    for (int k0 = 0; k0 < K; k0 += BK) {
#pragma unroll
        for (int u = 0; u < AE; u++) {
            int idx = tid + u*THREADS;
            int r = idx / BK, c = idx % BK;
            float v = 0.f;
            int gr = row0 + r;
            if (gr < M) v = A[(size_t)gr*K + k0 + c];
            As[c][r] = v;
        }
#pragma unroll
        for (int u = 0; u < BE; u++) {
            int idx = tid + u*THREADS;
            int r = idx / BN, c = idx % BN;
            float v = 0.f;
            int gc = col0 + c;
            if (gc < N) v = B[(size_t)(k0 + r)*N + gc];
            Bs[r][c] = v;
        }
        __syncthreads();
#pragma unroll
        for (int kk = 0; kk < BK; kk++) {
            float af[TM], bf[TN];
#pragma unroll
            for (int i = 0; i < TM; i += 4)
                *reinterpret_cast<float4*>(&af[i]) =
                    *reinterpret_cast<const float4*>(&As[kk][ty*TM + i]);
#pragma unroll
            for (int j = 0; j < TN; j += 4)
                *reinterpret_cast<float4*>(&bf[j]) =
                    *reinterpret_cast<const float4*>(&Bs[kk][tx*TN + j]);
#pragma unroll
            for (int i = 0; i < TM; i++)
#pragma unroll
                for (int j = 0; j < TN; j++)
                    acc[i][j] += af[i] * bf[j];
        }
        __syncthreads();
    }
#pragma unroll
    for (int i = 0; i < TM; i++) {
        int gr = row0 + ty*TM + i;
        if (gr >= M) continue;
#pragma unroll
        for (int j = 0; j < TN; j++) {
            int gc = col0 + tx*TN + j;
            if (gc >= N) continue;
            float v = acc[i][j];
            if (bias) v += bias[gc];
            if (ACT == 1) v = tanhf(v);
            C[(size_t)gr*N + gc] = v;
        }
    }
}

// ---------------- bilinear GEMM via fp16 mma ----------
// Round-13 structure; t fragments hoisted into registers for the whole
// j-block (invariant across its 32 iterations) -> zero t-LDS in inner loop.
#define BIL_BUF   24576u                    // per stage: 2 chunks x 12KB
#define BIL_SH_OFF (3*24576)
#define BIL_ST_OFF (3*24576 + 34816)
#define BIL_SMEM   (3*24576 + 2*34816)      // 143360

__device__ __forceinline__ void bil_load2(uint32_t sb, int it, int col0, int tid)
{
    uint32_t dH = sb + (uint32_t)(it % 3)*BIL_BUF;
#pragma unroll
    for (int half = 0; half < 2; ++half) {
        int c = it*2 + half;
#pragma unroll
        for (int p = 0; p < 3; p++) {
            int idx = tid + p*256;
            int n = idx >> 3, seg = idx & 7;
            size_t go = (size_t)(col0 + n)*(KBIL/2) + (size_t)c*32 + seg*4;
            CPA16(dH + half*12288u + SWZ((uint32_t)(n*128 + seg*16)), g_WbilHi + go);
        }
    }
}

__global__ void __launch_bounds__(256, 1)
k_bilinear_mma(const float* __restrict__ h, const float* __restrict__ t,
               const float* __restrict__ bias, float* __restrict__ out)
{
    extern __shared__ char smem[];
    uint32_t sb = smem_u32(smem);
    float* s_h = (float*)(smem + BIL_SH_OFF);   // [128][68]
    float* s_t = (float*)(smem + BIL_ST_OFF);   // [128][68]
    int tid = threadIdx.x, lid = tid & 31, wid = tid >> 5;
    int row0 = blockIdx.y * 128, col0 = blockIdx.x * 96;
    int wm = (wid >> 1) * 32;
    int wn = (wid & 1) * 48;
    int msel = lid >> 3, r8 = lid & 7;

    float acc[2][6][4];
#pragma unroll
    for (int i = 0; i < 2; i++)
#pragma unroll
        for (int n = 0; n < 6; n++)
#pragma unroll
            for (int q = 0; q < 4; q++) acc[i][n][q] = 0.f;

    float2 tt[4][2][4];   // [s][i][ta,tb,tc,td] — register-resident per j-block

    // prologue: stages 0 and 1 in flight
    bil_load2(sb, 0, col0, tid);
    asm volatile("cp.async.commit_group;");
    bil_load2(sb, 1, col0, tid);
    asm volatile("cp.async.commit_group;");

#pragma unroll 1
    for (int it = 0; it < NITER; ++it) {
        asm volatile("cp.async.wait_group 1;");   // stage `it` ready
        __syncthreads();                          // all warps past it-1 compute

        if ((it & 31) == 0) {                     // new j-block
            int j = it >> 5;
            for (int idx = tid; idx < 128*16; idx += 256) {
                int rr = idx >> 4, cc = (idx & 15) * 4;
                *(float4*)&s_h[rr*68 + cc] =
                    *(const float4*)&h[(size_t)(row0+rr)*EMB + j*64 + cc];
                *(float4*)&s_t[rr*68 + cc] =
                    *(const float4*)&t[(size_t)(row0+rr)*EMB + j*64 + cc];
            }
            __syncthreads();
            // hoist t fragments for the entire j-block
#pragma unroll
            for (int s = 0; s < 4; ++s)
#pragma unroll
                for (int i = 0; i < 2; ++i) {
                    int rb = (wm + i*16 + (lid >> 2))*68;
                    int cc = s*16 + (lid & 3)*2;
                    tt[s][i][0] = *(float2*)&s_t[rb + cc];
                    tt[s][i][1] = *(float2*)&s_t[rb + cc + 8];
                    tt[s][i][2] = *(float2*)&s_t[rb + 8*68 + cc];
                    tt[s][i][3] = *(float2*)&s_t[rb + 8*68 + cc + 8];
                }
        }

        uint32_t stage = sb + (uint32_t)(it % 3)*BIL_BUF;
        int a0c = (it*2)     & 63;
        int a1c = (it*2 + 1) & 63;
        float hv[2][2][2];   // [half][hi-lo row][i]
#pragma unroll
        for (int i = 0; i < 2; i++) {
            int r0 = wm + i*16 + (lid >> 2);
            hv[0][0][i] = s_h[r0*68 + a0c];
            hv[0][1][i] = s_h[(r0 + 8)*68 + a0c];
            hv[1][0][i] = s_h[r0*68 + a1c];
            hv[1][1][i] = s_h[(r0 + 8)*68 + a1c];
        }

#pragma unroll
        for (int s = 0; s < 4; ++s) {
#pragma unroll
            for (int half = 0; half < 2; ++half) {
                uint32_t bbase = stage + half*12288u;
                uint32_t bh[12];
#pragma unroll
                for (int pq = 0; pq < 3; ++pq) {
                    uint32_t off = SWZ((uint32_t)((wn + (pq*2 + (msel >> 1))*8 + r8)*128
                                                  + s*32 + (msel & 1)*16));
                    LDX4(&bh[pq*4], bbase + off);
                }
#pragma unroll
                for (int i = 0; i < 2; ++i) {
                    float h0 = hv[half][0][i], h1 = hv[half][1][i];
                    uint32_t ah[4];
                    ah[0] = pack_h2(h0*tt[s][i][0].x, h0*tt[s][i][0].y);
                    ah[1] = pack_h2(h1*tt[s][i][2].x, h1*tt[s][i][2].y);
                    ah[2] = pack_h2(h0*tt[s][i][1].x, h0*tt[s][i][1].y);
                    ah[3] = pack_h2(h1*tt[s][i][3].x, h1*tt[s][i][3].y);
#pragma unroll
                    for (int n = 0; n < 6; ++n)
                        MMA16816H(acc[i][n], ah[0],ah[1],ah[2],ah[3], bh[n*2], bh[n*2+1]);
                }
            }
        }

        // issue stage it+2 AFTER compute (proven faster position)
        if (it + 2 < NITER) bil_load2(sb, it + 2, col0, tid);
        asm volatile("cp.async.commit_group;");
    }

#pragma unroll
    for (int i = 0; i < 2; ++i) {
        int gr = row0 + wm + i*16 + (lid >> 2);
#pragma unroll
        for (int n = 0; n < 6; ++n) {
            int gc = col0 + wn + n*8 + (lid & 3)*2;
            float2 v0 = make_float2(acc[i][n][0] + bias[gc],
                                    acc[i][n][1] + bias[gc+1]);
            float2 v1 = make_float2(acc[i][n][2] + bias[gc],
                                    acc[i][n][3] + bias[gc+1]);
            *(float2*)&out[(size_t)gr*EMB + gc]     = v0;
            *(float2*)&out[(size_t)(gr+8)*EMB + gc] = v1;
        }
    }
}

// ---------------- launch ----------------
extern "C" void kernel_launch(void* const* d_in, const int* in_sizes, int n_in,
                              void* d_out, int out_size)
{
    const float* seq    = (const float*)d_in[0];
    const float* ent    = (const float*)d_in[1];
    const float* attn   = (const float*)d_in[2];
    const int*   labels = (const int*)  d_in[3];
    const int*   hts    = (const int*)  d_in[4];
    const float* W_head = (const float*)d_in[5];
    const float* b_head = (const float*)d_in[6];
    const float* W_tail = (const float*)d_in[7];
    const float* b_tail = (const float*)d_in[8];
    const float* W_bil  = (const float*)d_in[9];
    const float* b_bil  = (const float*)d_in[10];
    const float* W_cls  = (const float*)d_in[11];
    const float* b_cls  = (const float*)d_in[12];
    const float* W_proj = (const float*)d_in[13];
    const float* b_proj = (const float*)d_in[14];

    float* out      = (float*)d_out;
    float* out_cls  = out + (size_t)NROW*EMB;
    float* out_proj = out_cls + (size_t)NROW*NCLS;

    void *p_rel, *p_ht, *p_biasht;
    void *p_WbHi, *p_WhtHi, *p_seqHi, *p_htaH, *p_XH;
    cudaGetSymbolAddress(&p_rel,   g_rel);
    cudaGetSymbolAddress(&p_ht,    g_ht);
    cudaGetSymbolAddress(&p_biasht,g_bias_ht);
    cudaGetSymbolAddress(&p_WbHi,  g_WbilHi);
    cudaGetSymbolAddress(&p_WhtHi, g_WhtHi);
    cudaGetSymbolAddress(&p_seqHi, g_seqTHi);
    cudaGetSymbolAddress(&p_htaH,  g_htaH);
    cudaGetSymbolAddress(&p_XH,    g_XH);

    cudaFuncSetAttribute(k_bilinear_mma,
                         cudaFuncAttributeMaxDynamicSharedMemorySize, BIL_SMEM);
    cudaFuncSetAttribute(k_gemm_h<0,128>,
                         cudaFuncAttributeMaxDynamicSharedMemorySize, 65536);
    cudaFuncSetAttribute(k_gemm_h<1,64>,
                         cudaFuncAttributeMaxDynamicSharedMemorySize, 49152);

    static cudaStream_t s1 = nullptr, s2 = nullptr;
    static cudaEvent_t evFork = nullptr, evSeq = nullptr, evJoin = nullptr,
                       evEnt = nullptr, evBil = nullptr, evProj = nullptr;
    if (!s1) {
        cudaStreamCreateWithFlags(&s1, cudaStreamNonBlocking);
        cudaStreamCreateWithFlags(&s2, cudaStreamNonBlocking);
        cudaEventCreateWithFlags(&evFork, cudaEventDisableTiming);
        cudaEventCreateWithFlags(&evSeq,  cudaEventDisableTiming);
        cudaEventCreateWithFlags(&evJoin, cudaEventDisableTiming);
        cudaEventCreateWithFlags(&evEnt,  cudaEventDisableTiming);
        cudaEventCreateWithFlags(&evBil,  cudaEventDisableTiming);
        cudaEventCreateWithFlags(&evProj, cudaEventDisableTiming);
    }

    cudaEventRecord(evFork, 0);
    cudaStreamWaitEvent(s1, evFork, 0);
    cudaStreamWaitEvent(s2, evFork, 0);

    // ---- s2: entity pooling (independent of attn path) ----
    k_ent_emb<<<dim3(NE, Bdoc), 256, 0, s2>>>(ent, labels);
    cudaEventRecord(evEnt, s2);

    // ---- s1: seq split (needed by rel), then weight splits ----
    k_splitT<<<dim3(Lseq/128, HID/64, Bdoc), 256, 0, s1>>>(seq,
        (uint32_t*)p_seqHi, Lseq, HID, (long)Lseq*HID, (long)HID*(Lseq/2));
    cudaEventRecord(evSeq, s1);
    k_bias2<<<3, 256, 0, s1>>>(b_head, b_tail);
    k_splitT<<<dim3(2*HID/128, EMB/64), 256, 0, s1>>>(W_head,
        (uint32_t*)p_WhtHi, 2*HID, EMB, 0, 0);
    k_splitT<<<dim3(2*HID/128, EMB/64), 256, 0, s1>>>(W_tail,
        (uint32_t*)p_WhtHi + (size_t)EMB*HID, 2*HID, EMB, 0, 0);
    k_splitT<<<dim3(KBIL/128, EMB/64), 256, 0, s1>>>(W_bil,
        (uint32_t*)p_WbHi, KBIL, EMB, 0, 0);
    cudaEventRecord(evJoin, s1);

    // ---- main: attention pooling chain ----
    k_attn_mean<<<dim3(NE, NH, Bdoc), 256>>>(attn, labels);
    k_hta<<<dim3(Rht, Bdoc), 256>>>(hts);

    // rel = hta @ seq (1-pass fp16, N-tile 128)
    cudaStreamWaitEvent(0, evSeq, 0);
    k_gemm_h<0,128><<<dim3(HID/128, Rht/128, Bdoc), 256, 65536>>>(
        (const uint32_t*)p_htaH, (const uint32_t*)p_seqHi,
        nullptr, (float*)p_rel,
        Lseq, HID, (long)Rht*(Lseq/2), (long)HID*(Lseq/2), (long)Rht*HID);

    cudaStreamWaitEvent(0, evEnt, 0);
    k_gather<<<NROW, 256>>>(hts);

    cudaStreamWaitEvent(0, evJoin, 0);

    // h and t in one launch (z = head/tail), 1-pass fp16, N-tile 64
    k_gemm_h<1,64><<<dim3(EMB/64, NROW/128, 2), 256, 49152>>>(
        (const uint32_t*)p_XH, (const uint32_t*)p_WhtHi,
        (const float*)p_biasht, (float*)p_ht,
        2*HID, EMB, (long)NROW*HID, (long)EMB*HID, (long)NROW*EMB);

    // bilinear (fp16 1-pass) -> d_out (embeds)
    k_bilinear_mma<<<dim3(EMB/96, NROW/128), 256, BIL_SMEM>>>(
        (const float*)p_ht, (const float*)p_ht + (size_t)NROW*EMB, b_bil, out);
    cudaEventRecord(evBil, 0);

    // proj on s1 (concurrent with cls)
    cudaStreamWaitEvent(s1, evBil, 0);
    sgemm<64,32,16,4,4,1><<<dim3(NPROJ/32, NROW/64), 128, 0, s1>>>(
        out, W_proj, b_proj, out_proj, NROW, NPROJ, EMB);
    cudaEventRecord(evProj, s1);

    // cls on main
    sgemm<64,32,16,4,4,0><<<dim3((NCLS+31)/32, NROW/64), 128>>>(
        out, W_cls, b_cls, out_cls, NROW, NCLS, EMB);
    cudaStreamWaitEvent(0, evProj, 0);
}

// round 15
// speedup vs baseline: 1.1385x; 1.1385x over previous
#include <cuda_runtime.h>
#include <cuda_bf16.h>
#include <cuda_fp16.h>
#include <math.h>
#include <stdint.h>

// ---------------- problem constants ----------------
#define Bdoc 4
#define Lseq 1024
#define Ment 128
#define Rht  512
#define HID  1024
#define NH   16
#define NE   42
#define EMB  768
#define NBLK 12
#define NCLS 97
#define NPROJ 128
#define NROW (Bdoc*Rht)   // 2048
#define KBIL (EMB*64)     // 49152
#define NITER 384         // bilinear iters (K=128 each)

// ---------------- scratch ----------------
__device__ float g_ent_emb[Bdoc*NE*HID];
__device__ float g_attn_mean[Bdoc*NE*NH*Lseq];
__device__ float g_rel[NROW*HID];
__device__ float g_ht[2*NROW*EMB];                    // h then t (fp32)
__device__ float g_bias_ht[2*EMB];
// packed fp16x2 operands
__device__ uint32_t g_WbilHi[(size_t)EMB*KBIL/2];     // 75.5 MB
__device__ uint32_t g_WhtHi[2*EMB*HID];
__device__ uint32_t g_seqTHi[Bdoc*HID*Lseq/2];
__device__ uint32_t g_htaH[NROW*Lseq/2];
__device__ uint32_t g_XH[2*NROW*HID];

// ---------------- helpers ----------------
__device__ __forceinline__ uint32_t smem_u32(const void* p) {
    uint32_t a;
    asm("{ .reg .u64 t; cvta.to.shared.u64 t, %1; cvt.u32.u64 %0, t; }"
        : "=r"(a) : "l"(p));
    return a;
}
#define SWZ(o) ((o) ^ ((((uint32_t)(o))>>3)&0x70))

#define MMA16816H(d, a0,a1,a2,a3, b0,b1) \
    asm volatile("mma.sync.aligned.m16n8k16.row.col.f32.f16.f16.f32 " \
        "{%0,%1,%2,%3},{%4,%5,%6,%7},{%8,%9},{%0,%1,%2,%3};" \
        : "+f"((d)[0]), "+f"((d)[1]), "+f"((d)[2]), "+f"((d)[3]) \
        : "r"(a0), "r"(a1), "r"(a2), "r"(a3), "r"(b0), "r"(b1))

#define LDX4(r, addr) \
    asm volatile("ldmatrix.sync.aligned.m8n8.x4.shared.b16 {%0,%1,%2,%3},[%4];" \
        : "=r"((r)[0]), "=r"((r)[1]), "=r"((r)[2]), "=r"((r)[3]) : "r"(addr))

#define CPA16(dst, src) \
    asm volatile("cp.async.cg.shared.global [%0], [%1], 16;" :: "r"(dst), "l"(src))

__device__ __forceinline__ uint32_t pack_h2(float x, float y) {
    uint32_t r;   // lo = x, hi = y
    asm("cvt.rn.f16x2.f32 %0, %1, %2;" : "=r"(r) : "f"(y), "f"(x));
    return r;
}
__device__ __forceinline__ uint32_t hmul2(uint32_t a, uint32_t b) {
    uint32_t r;
    asm("mul.rn.f16x2 %0, %1, %2;" : "=r"(r) : "r"(a), "r"(b));
    return r;
}

// ---------------- K1: entity logsumexp pooling ----------------
__global__ void k_ent_emb(const float* __restrict__ ent,
                          const int* __restrict__ labels)
{
    int e = blockIdx.x, b = blockIdx.y;
    __shared__ int s_idx[Ment];
    __shared__ int s_cnt;
    int tid = threadIdx.x;
    if (tid == 0) {
        int c = 0;
        for (int i = 0; i < Ment; i++)
            if (labels[b*Ment + i] == e) s_idx[c++] = i;
        s_cnt = c;
    }
    __syncthreads();
    int cnt = s_cnt;
    const float* eb = ent + (size_t)b*Ment*HID;
    float* out = g_ent_emb + ((size_t)(b*NE + e))*HID;
    for (int d = tid; d < HID; d += blockDim.x) {
        float r;
        if (cnt == 0) {
            r = 0.f;
        } else {
            float mx = -3.4e38f, s = 0.f;
            for (int i = 0; i < cnt; i++) {
                float v = eb[(size_t)s_idx[i]*HID + d];
                if (v > mx) { s = s*expf(mx - v) + 1.f; mx = v; }
                else        { s += expf(v - mx); }
            }
            r = mx + logf(s);
        }
        out[d] = r;
    }
}

// ---------------- K2: per-entity mean attention ----------------
__global__ void k_attn_mean(const float* __restrict__ attn,
                            const int* __restrict__ labels)
{
    int e = blockIdx.x, h = blockIdx.y, b = blockIdx.z;
    __shared__ int s_idx[Ment];
    __shared__ int s_cnt;
    int tid = threadIdx.x;
    if (tid == 0) {
        int c = 0;
        for (int i = 0; i < Ment; i++)
            if (labels[b*Ment + i] == e) s_idx[c++] = i;
        s_cnt = c;
    }
    __syncthreads();
    int cnt = s_cnt;
    float inv = 1.f / (float)(cnt > 0 ? cnt : 1);
    const float* ab = attn + (((size_t)b*NH + h)*Ment)*Lseq;
    float* out = g_attn_mean + (((size_t)(b*NE + e))*NH + h)*Lseq;
    for (int l = tid; l < Lseq; l += blockDim.x) {
        float s = 0.f;
        for (int i = 0; i < cnt; i++) s += ab[(size_t)s_idx[i]*Lseq + l];
        out[l] = s * inv;
    }
}

// ---------------- K3: hta -> single fp16 ----------------
__global__ void k_hta(const int* __restrict__ hts)
{
    int r = blockIdx.x, b = blockIdx.y;
    int r2 = b*Rht + r;
    int e0 = hts[(size_t)r2*2 + 0];
    int e1 = hts[(size_t)r2*2 + 1];
    const float* a0 = g_attn_mean + ((size_t)(b*NE + e0))*NH*Lseq;
    const float* a1 = g_attn_mean + ((size_t)(b*NE + e1))*NH*Lseq;
    int tid = threadIdx.x;
    int l0 = tid*4;
    float4 acc = make_float4(0.f,0.f,0.f,0.f);
#pragma unroll
    for (int h = 0; h < NH; h++) {
        float4 x = *(const float4*)&a0[h*Lseq + l0];
        float4 y = *(const float4*)&a1[h*Lseq + l0];
        acc.x += x.x*y.x; acc.y += x.y*y.y;
        acc.z += x.z*y.z; acc.w += x.w*y.w;
    }
    acc.x *= (1.f/NH); acc.y *= (1.f/NH); acc.z *= (1.f/NH); acc.w *= (1.f/NH);
    __shared__ float red[256];
    red[tid] = acc.x + acc.y + acc.z + acc.w;
    __syncthreads();
    for (int o = 128; o > 0; o >>= 1) {
        if (tid < o) red[tid] += red[tid + o];
        __syncthreads();
    }
    float sc = 1.f / (red[0] + 1e-5f);
    size_t o = (size_t)r2*(Lseq/2) + tid*2;
    g_htaH[o]   = pack_h2(acc.x*sc, acc.y*sc);
    g_htaH[o+1] = pack_h2(acc.z*sc, acc.w*sc);
}

// ---------------- K5: gather -> single fp16 X ----------------
__global__ void k_gather(const int* __restrict__ hts)
{
    int r2 = blockIdx.x;
    int b = r2 / Rht;
    int e0 = hts[(size_t)r2*2 + 0];
    int e1 = hts[(size_t)r2*2 + 1];
    const float* emb0 = g_ent_emb + ((size_t)(b*NE + e0))*HID;
    const float* emb1 = g_ent_emb + ((size_t)(b*NE + e1))*HID;
    const float* rel  = g_rel + (size_t)r2*HID;
    for (int u = threadIdx.x; u < HID; u += 256) {
        if (u < HID/2) {
            float2 v0 = *(const float2*)&emb0[2*u];
            g_XH[(size_t)r2*HID + u] = pack_h2(v0.x, v0.y);
            float2 v1 = *(const float2*)&emb1[2*u];
            g_XH[(size_t)(NROW + r2)*HID + u] = pack_h2(v1.x, v1.y);
        } else {
            float2 rv = *(const float2*)&rel[2*u - HID];
            uint32_t p = pack_h2(rv.x, rv.y);
            g_XH[(size_t)r2*HID + u] = p;
            g_XH[(size_t)(NROW + r2)*HID + u] = p;
        }
    }
}

// ---------------- split + transpose: [z][K][N] f32 -> [z][N][K/2] fp16x2 ----
__global__ void __launch_bounds__(256)
k_splitT(const float* __restrict__ in, uint32_t* __restrict__ outHi,
         int K, int N, long sIn, long sOut)
{
    __shared__ float s[128][65];
    in    += (size_t)blockIdx.z * sIn;
    outHi += (size_t)blockIdx.z * sOut;
    int k0 = blockIdx.x*128, n0 = blockIdx.y*64;
    int tid = threadIdx.x;
#pragma unroll
    for (int u = 0; u < 8; u++) {
        int idx = tid + u*256;
        int kk = idx >> 4;
        int cc = (idx & 15) * 4;
        float4 v = *(const float4*)&in[(size_t)(k0+kk)*N + n0 + cc];
        s[kk][cc+0] = v.x; s[kk][cc+1] = v.y;
        s[kk][cc+2] = v.z; s[kk][cc+3] = v.w;
    }
    __syncthreads();
    int K2 = K >> 1;
#pragma unroll
    for (int u = 0; u < 4; u++) {
        int idx = tid + u*256;
        int nn = idx >> 4, q = idx & 15;
        uint32_t hi[4];
#pragma unroll
        for (int i = 0; i < 4; i++)
            hi[i] = pack_h2(s[q*8 + i*2][nn], s[q*8 + i*2 + 1][nn]);
        size_t o = (size_t)(n0+nn)*K2 + (k0 >> 1) + q*4;
        *(uint4*)&outHi[o] = make_uint4(hi[0], hi[1], hi[2], hi[3]);
    }
}

__global__ void k_bias2(const float* __restrict__ b0, const float* __restrict__ b1)
{
    int i = threadIdx.x + blockIdx.x*256;
    if (i < EMB) { g_bias_ht[i] = b0[i]; g_bias_ht[EMB+i] = b1[i]; }
}

// ---------------- 1-pass fp16 mma GEMM, templated N-tile (round-10) -------
template<int ACT, int NT>
__global__ void __launch_bounds__(256, 1)
k_gemm_h(const uint32_t* __restrict__ Ah, const uint32_t* __restrict__ Bh,
         const float* __restrict__ bias, float* __restrict__ C,
         int K, int N, long sA, long sB, long sC)
{
    constexpr int NFR  = NT/16;
    constexpr int BUFB = 16384 + NT*128;
    extern __shared__ char smem[];
    uint32_t sb = smem_u32(smem);
    int tid = threadIdx.x, lid = tid & 31, wid = tid >> 5;
    int row0 = blockIdx.y*128, col0 = blockIdx.x*NT;
    Ah += (size_t)blockIdx.z * sA;
    Bh += (size_t)blockIdx.z * sB;
    C  += (size_t)blockIdx.z * sC;
    const float* bz = bias ? bias + (size_t)blockIdx.z * N : nullptr;
    int K2 = K >> 1, nchunk = K >> 6;
    int wm = (wid >> 1)*32, wn = (wid & 1)*(NT/2);
    int msel = lid >> 3, r8 = lid & 7;

    float acc[2][NFR][4];
#pragma unroll
    for (int i = 0; i < 2; i++)
#pragma unroll
        for (int n = 0; n < NFR; n++)
#pragma unroll
            for (int q = 0; q < 4; q++) acc[i][n][q] = 0.f;

#define GLOADH(c) { \
    uint32_t base = sb + (uint32_t)((c)&1)*BUFB; \
    _Pragma("unroll") \
    for (int p = 0; p < 4; p++) { \
        int idx = tid + p*256; int r = idx >> 3, seg = idx & 7; \
        size_t goA = (size_t)(row0+r)*K2 + (size_t)(c)*32 + seg*4; \
        CPA16(base + SWZ((uint32_t)(r*128 + seg*16)), Ah + goA); \
    } \
    _Pragma("unroll") \
    for (int p = 0; p < NT/32; p++) { \
        int idx = tid + p*256; int r = idx >> 3, seg = idx & 7; \
        size_t goB = (size_t)(col0+r)*K2 + (size_t)(c)*32 + seg*4; \
        CPA16(base + 16384u + SWZ((uint32_t)(r*128 + seg*16)), Bh + goB); \
    } }

    GLOADH(0);
    asm volatile("cp.async.commit_group;");

#pragma unroll 1
    for (int c = 0; c < nchunk; ++c) {
        if (c + 1 < nchunk) GLOADH(c + 1);
        asm volatile("cp.async.commit_group;");
        asm volatile("cp.async.wait_group 1;");
        __syncthreads();

        uint32_t abase = sb + (uint32_t)(c & 1)*BUFB;
        uint32_t bbase = abase + 16384u;
#pragma unroll
        for (int s = 0; s < 4; ++s) {
            uint32_t ah[2][4];
#pragma unroll
            for (int i = 0; i < 2; ++i) {
                uint32_t off = SWZ((uint32_t)((wm + i*16 + (lid & 15))*128
                                              + s*32 + (lid >> 4)*16));
                LDX4(ah[i], abase + off);
            }
            uint32_t bh[2*NFR];
#pragma unroll
            for (int pq = 0; pq < NT/32; ++pq) {
                uint32_t off = SWZ((uint32_t)((wn + (pq*2 + (msel >> 1))*8 + r8)*128
                                              + s*32 + (msel & 1)*16));
                LDX4(&bh[pq*4], bbase + off);
            }
#pragma unroll
            for (int i = 0; i < 2; ++i)
#pragma unroll
                for (int n = 0; n < NFR; ++n)
                    MMA16816H(acc[i][n], ah[i][0],ah[i][1],ah[i][2],ah[i][3], bh[n*2], bh[n*2+1]);
        }
        __syncthreads();
    }
#undef GLOADH

#pragma unroll
    for (int i = 0; i < 2; ++i) {
        int gr = row0 + wm + i*16 + (lid >> 2);
#pragma unroll
        for (int n = 0; n < NFR; ++n) {
            int gc = col0 + wn + n*8 + (lid & 3)*2;
            float b0v = bz ? bz[gc] : 0.f, b1v = bz ? bz[gc+1] : 0.f;
            float v0 = acc[i][n][0] + b0v, v1 = acc[i][n][1] + b1v;
            float v2 = acc[i][n][2] + b0v, v3 = acc[i][n][3] + b1v;
            if (ACT == 1) { v0 = tanhf(v0); v1 = tanhf(v1); v2 = tanhf(v2); v3 = tanhf(v3); }
            *(float2*)&C[(size_t)gr*N + gc]     = make_float2(v0, v1);
            *(float2*)&C[(size_t)(gr+8)*N + gc] = make_float2(v2, v3);
        }
    }
}

// ---------------- fp32 SIMT sgemm (small tails: cls/proj) ----------------
template<int BM, int BN, int BK, int TM, int TN, int ACT>
__global__ __launch_bounds__((BM/TM)*(BN/TN))
void sgemm(const float* __restrict__ A, const float* __restrict__ B,
           const float* __restrict__ bias, float* __restrict__ C,
           int M, int N, int K)
{
    constexpr int THREADS = (BM/TM)*(BN/TN);
    __shared__ float As[BK][BM + 4];
    __shared__ float Bs[BK][BN];
    int tid = threadIdx.x;
    int tx = tid % (BN/TN);
    int ty = tid / (BN/TN);
    int row0 = blockIdx.y * BM, col0 = blockIdx.x * BN;
    float acc[TM][TN] = {};
    constexpr int AE = BM*BK/THREADS;
    constexpr int BE = BK*BN/THREADS;

    for (int k0 = 0; k0 < K; k0 += BK) {
#pragma unroll
        for (int u = 0; u < AE; u++) {
            int idx = tid + u*THREADS;
            int r = idx / BK, c = idx % BK;
            float v = 0.f;
            int gr = row0 + r;
            if (gr < M) v = A[(size_t)gr*K + k0 + c];
            As[c][r] = v;
        }
#pragma unroll
        for (int u = 0; u < BE; u++) {
            int idx = tid + u*THREADS;
            int r = idx / BN, c = idx % BN;
            float v = 0.f;
            int gc = col0 + c;
            if (gc < N) v = B[(size_t)(k0 + r)*N + gc];
            Bs[r][c] = v;
        }
        __syncthreads();
#pragma unroll
        for (int kk = 0; kk < BK; kk++) {
            float af[TM], bf[TN];
#pragma unroll
            for (int i = 0; i < TM; i += 4)
                *reinterpret_cast<float4*>(&af[i]) =
                    *reinterpret_cast<const float4*>(&As[kk][ty*TM + i]);
#pragma unroll
            for (int j = 0; j < TN; j += 4)
                *reinterpret_cast<float4*>(&bf[j]) =
                    *reinterpret_cast<const float4*>(&Bs[kk][tx*TN + j]);
#pragma unroll
            for (int i = 0; i < TM; i++)
#pragma unroll
                for (int j = 0; j < TN; j++)
                    acc[i][j] += af[i] * bf[j];
        }
        __syncthreads();
    }
#pragma unroll
    for (int i = 0; i < TM; i++) {
        int gr = row0 + ty*TM + i;
        if (gr >= M) continue;
#pragma unroll
        for (int j = 0; j < TN; j++) {
            int gc = col0 + tx*TN + j;
            if (gc >= N) continue;
            float v = acc[i][j];
            if (bias) v += bias[gc];
            if (ACT == 1) v = tanhf(v);
            C[(size_t)gr*N + gc] = v;
        }
    }
}

// ---------------- bilinear GEMM via fp16 mma ----------
// Round-13 structure; t stored in SMEM as fp16x2 (converted once per
// j-block) and A fragments formed with HMUL2 (1 op) instead of
// 2 FMUL + 1 cvt. Inner-loop ALU drops ~120 ops/thread/iter.
#define BIL_BUF   24576u                    // per stage: 2 chunks x 12KB
#define BIL_SH_OFF (3*24576)
#define BIL_ST_OFF (3*24576 + 34816)        // s_t: uint32[128][36] = 18432 B
#define BIL_SMEM   (3*24576 + 34816 + 18432)  // 126976

__device__ __forceinline__ void bil_load2(uint32_t sb, int it, int col0, int tid)
{
    uint32_t dH = sb + (uint32_t)(it % 3)*BIL_BUF;
#pragma unroll
    for (int half = 0; half < 2; ++half) {
        int c = it*2 + half;
#pragma unroll
        for (int p = 0; p < 3; p++) {
            int idx = tid + p*256;
            int n = idx >> 3, seg = idx & 7;
            size_t go = (size_t)(col0 + n)*(KBIL/2) + (size_t)c*32 + seg*4;
            CPA16(dH + half*12288u + SWZ((uint32_t)(n*128 + seg*16)), g_WbilHi + go);
        }
    }
}

__global__ void __launch_bounds__(256, 1)
k_bilinear_mma(const float* __restrict__ h, const float* __restrict__ t,
               const float* __restrict__ bias, float* __restrict__ out)
{
    extern __shared__ char smem[];
    uint32_t sb = smem_u32(smem);
    float* s_h = (float*)(smem + BIL_SH_OFF);        // [128][68] fp32
    uint32_t* s_t = (uint32_t*)(smem + BIL_ST_OFF);  // [128][36] fp16x2
    int tid = threadIdx.x, lid = tid & 31, wid = tid >> 5;
    int row0 = blockIdx.y * 128, col0 = blockIdx.x * 96;
    int wm = (wid >> 1) * 32;
    int wn = (wid & 1) * 48;
    int msel = lid >> 3, r8 = lid & 7;

    float acc[2][6][4];
#pragma unroll
    for (int i = 0; i < 2; i++)
#pragma unroll
        for (int n = 0; n < 6; n++)
#pragma unroll
            for (int q = 0; q < 4; q++) acc[i][n][q] = 0.f;

    // prologue: stages 0 and 1 in flight
    bil_load2(sb, 0, col0, tid);
    asm volatile("cp.async.commit_group;");
    bil_load2(sb, 1, col0, tid);
    asm volatile("cp.async.commit_group;");

#pragma unroll 1
    for (int it = 0; it < NITER; ++it) {
        asm volatile("cp.async.wait_group 1;");   // stage `it` ready
        __syncthreads();                          // all warps past it-1 compute

        if ((it & 31) == 0) {                     // new j-block: reload h (fp32) + t (fp16x2)
            int j = it >> 5;
            for (int idx = tid; idx < 128*16; idx += 256) {
                int rr = idx >> 4, cc = (idx & 15) * 4;
                *(float4*)&s_h[rr*68 + cc] =
                    *(const float4*)&h[(size_t)(row0+rr)*EMB + j*64 + cc];
                float4 tv = *(const float4*)&t[(size_t)(row0+rr)*EMB + j*64 + cc];
                uint32_t p0 = pack_h2(tv.x, tv.y);
                uint32_t p1 = pack_h2(tv.z, tv.w);
                s_t[rr*36 + (cc >> 1)]     = p0;
                s_t[rr*36 + (cc >> 1) + 1] = p1;
            }
            __syncthreads();
        }

        uint32_t stage = sb + (uint32_t)(it % 3)*BIL_BUF;
        int a0c = (it*2)     & 63;
        int a1c = (it*2 + 1) & 63;
        // h scalars -> duplicated fp16x2 registers (8 cvt per iteration)
        uint32_t hd[2][2][2];   // [half][hi-lo row][i]
#pragma unroll
        for (int i = 0; i < 2; i++) {
            int r0 = wm + i*16 + (lid >> 2);
            float v;
            v = s_h[r0*68 + a0c];       hd[0][0][i] = pack_h2(v, v);
            v = s_h[(r0 + 8)*68 + a0c]; hd[0][1][i] = pack_h2(v, v);
            v = s_h[r0*68 + a1c];       hd[1][0][i] = pack_h2(v, v);
            v = s_h[(r0 + 8)*68 + a1c]; hd[1][1][i] = pack_h2(v, v);
        }

#pragma unroll
        for (int s = 0; s < 4; ++s) {
            // t fragments (fp16x2): loaded once per s, shared by both halves
            uint32_t tt[2][4];   // [i][ta,tb,tc,td]
#pragma unroll
            for (int i = 0; i < 2; ++i) {
                int rb = (wm + i*16 + (lid >> 2))*36;
                int cq = s*8 + (lid & 3);
                tt[i][0] = s_t[rb + cq];
                tt[i][1] = s_t[rb + cq + 4];
                tt[i][2] = s_t[rb + 8*36 + cq];
                tt[i][3] = s_t[rb + 8*36 + cq + 4];
            }
#pragma unroll
            for (int half = 0; half < 2; ++half) {
                uint32_t bbase = stage + half*12288u;
                uint32_t bh[12];
#pragma unroll
                for (int pq = 0; pq < 3; ++pq) {
                    uint32_t off = SWZ((uint32_t)((wn + (pq*2 + (msel >> 1))*8 + r8)*128
                                                  + s*32 + (msel & 1)*16));
                    LDX4(&bh[pq*4], bbase + off);
                }
#pragma unroll
                for (int i = 0; i < 2; ++i) {
                    uint32_t ah[4];
                    ah[0] = hmul2(hd[half][0][i], tt[i][0]);
                    ah[1] = hmul2(hd[half][1][i], tt[i][2]);
                    ah[2] = hmul2(hd[half][0][i], tt[i][1]);
                    ah[3] = hmul2(hd[half][1][i], tt[i][3]);
#pragma unroll
                    for (int n = 0; n < 6; ++n)
                        MMA16816H(acc[i][n], ah[0],ah[1],ah[2],ah[3], bh[n*2], bh[n*2+1]);
                }
            }
        }

        // issue stage it+2 AFTER compute (proven faster position)
        if (it + 2 < NITER) bil_load2(sb, it + 2, col0, tid);
        asm volatile("cp.async.commit_group;");
    }

#pragma unroll
    for (int i = 0; i < 2; ++i) {
        int gr = row0 + wm + i*16 + (lid >> 2);
#pragma unroll
        for (int n = 0; n < 6; ++n) {
            int gc = col0 + wn + n*8 + (lid & 3)*2;
            float2 v0 = make_float2(acc[i][n][0] + bias[gc],
                                    acc[i][n][1] + bias[gc+1]);
            float2 v1 = make_float2(acc[i][n][2] + bias[gc],
                                    acc[i][n][3] + bias[gc+1]);
            *(float2*)&out[(size_t)gr*EMB + gc]     = v0;
            *(float2*)&out[(size_t)(gr+8)*EMB + gc] = v1;
        }
    }
}

// ---------------- launch ----------------
extern "C" void kernel_launch(void* const* d_in, const int* in_sizes, int n_in,
                              void* d_out, int out_size)
{
    const float* seq    = (const float*)d_in[0];
    const float* ent    = (const float*)d_in[1];
    const float* attn   = (const float*)d_in[2];
    const int*   labels = (const int*)  d_in[3];
    const int*   hts    = (const int*)  d_in[4];
    const float* W_head = (const float*)d_in[5];
    const float* b_head = (const float*)d_in[6];
    const float* W_tail = (const float*)d_in[7];
    const float* b_tail = (const float*)d_in[8];
    const float* W_bil  = (const float*)d_in[9];
    const float* b_bil  = (const float*)d_in[10];
    const float* W_cls  = (const float*)d_in[11];
    const float* b_cls  = (const float*)d_in[12];
    const float* W_proj = (const float*)d_in[13];
    const float* b_proj = (const float*)d_in[14];

    float* out      = (float*)d_out;
    float* out_cls  = out + (size_t)NROW*EMB;
    float* out_proj = out_cls + (size_t)NROW*NCLS;

    void *p_rel, *p_ht, *p_biasht;
    void *p_WbHi, *p_WhtHi, *p_seqHi, *p_htaH, *p_XH;
    cudaGetSymbolAddress(&p_rel,   g_rel);
    cudaGetSymbolAddress(&p_ht,    g_ht);
    cudaGetSymbolAddress(&p_biasht,g_bias_ht);
    cudaGetSymbolAddress(&p_WbHi,  g_WbilHi);
    cudaGetSymbolAddress(&p_WhtHi, g_WhtHi);
    cudaGetSymbolAddress(&p_seqHi, g_seqTHi);
    cudaGetSymbolAddress(&p_htaH,  g_htaH);
    cudaGetSymbolAddress(&p_XH,    g_XH);

    cudaFuncSetAttribute(k_bilinear_mma,
                         cudaFuncAttributeMaxDynamicSharedMemorySize, BIL_SMEM);
    cudaFuncSetAttribute(k_gemm_h<0,128>,
                         cudaFuncAttributeMaxDynamicSharedMemorySize, 65536);
    cudaFuncSetAttribute(k_gemm_h<1,64>,
                         cudaFuncAttributeMaxDynamicSharedMemorySize, 49152);

    static cudaStream_t s1 = nullptr, s2 = nullptr;
    static cudaEvent_t evFork = nullptr, evSeq = nullptr, evJoin = nullptr,
                       evEnt = nullptr, evBil = nullptr, evProj = nullptr;
    if (!s1) {
        cudaStreamCreateWithFlags(&s1, cudaStreamNonBlocking);
        cudaStreamCreateWithFlags(&s2, cudaStreamNonBlocking);
        cudaEventCreateWithFlags(&evFork, cudaEventDisableTiming);
        cudaEventCreateWithFlags(&evSeq,  cudaEventDisableTiming);
        cudaEventCreateWithFlags(&evJoin, cudaEventDisableTiming);
        cudaEventCreateWithFlags(&evEnt,  cudaEventDisableTiming);
        cudaEventCreateWithFlags(&evBil,  cudaEventDisableTiming);
        cudaEventCreateWithFlags(&evProj, cudaEventDisableTiming);
    }

    cudaEventRecord(evFork, 0);
    cudaStreamWaitEvent(s1, evFork, 0);
    cudaStreamWaitEvent(s2, evFork, 0);

    // ---- s2: entity pooling (independent of attn path) ----
    k_ent_emb<<<dim3(NE, Bdoc), 256, 0, s2>>>(ent, labels);
    cudaEventRecord(evEnt, s2);

    // ---- s1: seq split (needed by rel), then weight splits ----
    k_splitT<<<dim3(Lseq/128, HID/64, Bdoc), 256, 0, s1>>>(seq,
        (uint32_t*)p_seqHi, Lseq, HID, (long)Lseq*HID, (long)HID*(Lseq/2));
    cudaEventRecord(evSeq, s1);
    k_bias2<<<3, 256, 0, s1>>>(b_head, b_tail);
    k_splitT<<<dim3(2*HID/128, EMB/64), 256, 0, s1>>>(W_head,
        (uint32_t*)p_WhtHi, 2*HID, EMB, 0, 0);
    k_splitT<<<dim3(2*HID/128, EMB/64), 256, 0, s1>>>(W_tail,
        (uint32_t*)p_WhtHi + (size_t)EMB*HID, 2*HID, EMB, 0, 0);
    k_splitT<<<dim3(KBIL/128, EMB/64), 256, 0, s1>>>(W_bil,
        (uint32_t*)p_WbHi, KBIL, EMB, 0, 0);
    cudaEventRecord(evJoin, s1);

    // ---- main: attention pooling chain ----
    k_attn_mean<<<dim3(NE, NH, Bdoc), 256>>>(attn, labels);
    k_hta<<<dim3(Rht, Bdoc), 256>>>(hts);

    // rel = hta @ seq (1-pass fp16, N-tile 128)
    cudaStreamWaitEvent(0, evSeq, 0);
    k_gemm_h<0,128><<<dim3(HID/128, Rht/128, Bdoc), 256, 65536>>>(
        (const uint32_t*)p_htaH, (const uint32_t*)p_seqHi,
        nullptr, (float*)p_rel,
        Lseq, HID, (long)Rht*(Lseq/2), (long)HID*(Lseq/2), (long)Rht*HID);

    cudaStreamWaitEvent(0, evEnt, 0);
    k_gather<<<NROW, 256>>>(hts);

    cudaStreamWaitEvent(0, evJoin, 0);

    // h and t in one launch (z = head/tail), 1-pass fp16, N-tile 64
    k_gemm_h<1,64><<<dim3(EMB/64, NROW/128, 2), 256, 49152>>>(
        (const uint32_t*)p_XH, (const uint32_t*)p_WhtHi,
        (const float*)p_biasht, (float*)p_ht,
        2*HID, EMB, (long)NROW*HID, (long)EMB*HID, (long)NROW*EMB);

    // bilinear (fp16 1-pass) -> d_out (embeds)
    k_bilinear_mma<<<dim3(EMB/96, NROW/128), 256, BIL_SMEM>>>(
        (const float*)p_ht, (const float*)p_ht + (size_t)NROW*EMB, b_bil, out);
    cudaEventRecord(evBil, 0);

    // proj on s1 (concurrent with cls)
    cudaStreamWaitEvent(s1, evBil, 0);
    sgemm<64,32,16,4,4,1><<<dim3(NPROJ/32, NROW/64), 128, 0, s1>>>(
        out, W_proj, b_proj, out_proj, NROW, NPROJ, EMB);
    cudaEventRecord(evProj, s1);

    // cls on main
    sgemm<64,32,16,4,4,0><<<dim3((NCLS+31)/32, NROW/64), 128>>>(
        out, W_cls, b_cls, out_cls, NROW, NCLS, EMB);
    cudaStreamWaitEvent(0, evProj, 0);
}

// round 16
// speedup vs baseline: 1.1533x; 1.0130x over previous
#include <cuda_runtime.h>
#include <cuda_bf16.h>
#include <cuda_fp16.h>
#include <math.h>
#include <stdint.h>

// ---------------- problem constants ----------------
#define Bdoc 4
#define Lseq 1024
#define Ment 128
#define Rht  512
#define HID  1024
#define NH   16
#define NE   42
#define EMB  768
#define NBLK 12
#define NCLS 97
#define NPROJ 128
#define NROW (Bdoc*Rht)   // 2048
#define KBIL (EMB*64)     // 49152
#define NITER 384         // bilinear iters (K=128 each)

// ---------------- scratch ----------------
__device__ float g_ent_emb[Bdoc*NE*HID];
__device__ float g_attn_mean[Bdoc*NE*NH*Lseq];
__device__ float g_rel[NROW*HID];
__device__ float g_ht[2*NROW*EMB];                    // h then t (fp32)
__device__ float g_bias_ht[2*EMB];
// packed fp16x2 operands
__device__ uint32_t g_WbilHi[(size_t)EMB*KBIL/2];     // 75.5 MB
__device__ uint32_t g_WhtHi[2*EMB*HID];
__device__ uint32_t g_seqTHi[Bdoc*HID*Lseq/2];
__device__ uint32_t g_htaH[NROW*Lseq/2];
__device__ uint32_t g_XH[2*NROW*HID];

// ---------------- helpers ----------------
__device__ __forceinline__ uint32_t smem_u32(const void* p) {
    uint32_t a;
    asm("{ .reg .u64 t; cvta.to.shared.u64 t, %1; cvt.u32.u64 %0, t; }"
        : "=r"(a) : "l"(p));
    return a;
}
#define SWZ(o) ((o) ^ ((((uint32_t)(o))>>3)&0x70))

#define MMA16816H(d, a0,a1,a2,a3, b0,b1) \
    asm volatile("mma.sync.aligned.m16n8k16.row.col.f32.f16.f16.f32 " \
        "{%0,%1,%2,%3},{%4,%5,%6,%7},{%8,%9},{%0,%1,%2,%3};" \
        : "+f"((d)[0]), "+f"((d)[1]), "+f"((d)[2]), "+f"((d)[3]) \
        : "r"(a0), "r"(a1), "r"(a2), "r"(a3), "r"(b0), "r"(b1))

#define LDX4(r, addr) \
    asm volatile("ldmatrix.sync.aligned.m8n8.x4.shared.b16 {%0,%1,%2,%3},[%4];" \
        : "=r"((r)[0]), "=r"((r)[1]), "=r"((r)[2]), "=r"((r)[3]) : "r"(addr))

#define CPA16(dst, src) \
    asm volatile("cp.async.cg.shared.global [%0], [%1], 16;" :: "r"(dst), "l"(src))

__device__ __forceinline__ uint32_t pack_h2(float x, float y) {
    uint32_t r;   // lo = x, hi = y
    asm("cvt.rn.f16x2.f32 %0, %1, %2;" : "=r"(r) : "f"(y), "f"(x));
    return r;
}
__device__ __forceinline__ uint32_t hmul2(uint32_t a, uint32_t b) {
    uint32_t r;
    asm("mul.rn.f16x2 %0, %1, %2;" : "=r"(r) : "r"(a), "r"(b));
    return r;
}

// ---------------- K1: entity logsumexp pooling ----------------
__global__ void k_ent_emb(const float* __restrict__ ent,
                          const int* __restrict__ labels)
{
    int e = blockIdx.x, b = blockIdx.y;
    __shared__ int s_idx[Ment];
    __shared__ int s_cnt;
    int tid = threadIdx.x;
    if (tid == 0) {
        int c = 0;
        for (int i = 0; i < Ment; i++)
            if (labels[b*Ment + i] == e) s_idx[c++] = i;
        s_cnt = c;
    }
    __syncthreads();
    int cnt = s_cnt;
    const float* eb = ent + (size_t)b*Ment*HID;
    float* out = g_ent_emb + ((size_t)(b*NE + e))*HID;
    for (int d = tid; d < HID; d += blockDim.x) {
        float r;
        if (cnt == 0) {
            r = 0.f;
        } else {
            float mx = -3.4e38f, s = 0.f;
            for (int i = 0; i < cnt; i++) {
                float v = eb[(size_t)s_idx[i]*HID + d];
                if (v > mx) { s = s*expf(mx - v) + 1.f; mx = v; }
                else        { s += expf(v - mx); }
            }
            r = mx + logf(s);
        }
        out[d] = r;
    }
}

// ---------------- K2: per-entity mean attention ----------------
__global__ void k_attn_mean(const float* __restrict__ attn,
                            const int* __restrict__ labels)
{
    int e = blockIdx.x, h = blockIdx.y, b = blockIdx.z;
    __shared__ int s_idx[Ment];
    __shared__ int s_cnt;
    int tid = threadIdx.x;
    if (tid == 0) {
        int c = 0;
        for (int i = 0; i < Ment; i++)
            if (labels[b*Ment + i] == e) s_idx[c++] = i;
        s_cnt = c;
    }
    __syncthreads();
    int cnt = s_cnt;
    float inv = 1.f / (float)(cnt > 0 ? cnt : 1);
    const float* ab = attn + (((size_t)b*NH + h)*Ment)*Lseq;
    float* out = g_attn_mean + (((size_t)(b*NE + e))*NH + h)*Lseq;
    for (int l = tid; l < Lseq; l += blockDim.x) {
        float s = 0.f;
        for (int i = 0; i < cnt; i++) s += ab[(size_t)s_idx[i]*Lseq + l];
        out[l] = s * inv;
    }
}

// ---------------- K3: hta -> single fp16 ----------------
__global__ void k_hta(const int* __restrict__ hts)
{
    int r = blockIdx.x, b = blockIdx.y;
    int r2 = b*Rht + r;
    int e0 = hts[(size_t)r2*2 + 0];
    int e1 = hts[(size_t)r2*2 + 1];
    const float* a0 = g_attn_mean + ((size_t)(b*NE + e0))*NH*Lseq;
    const float* a1 = g_attn_mean + ((size_t)(b*NE + e1))*NH*Lseq;
    int tid = threadIdx.x;
    int l0 = tid*4;
    float4 acc = make_float4(0.f,0.f,0.f,0.f);
#pragma unroll
    for (int h = 0; h < NH; h++) {
        float4 x = *(const float4*)&a0[h*Lseq + l0];
        float4 y = *(const float4*)&a1[h*Lseq + l0];
        acc.x += x.x*y.x; acc.y += x.y*y.y;
        acc.z += x.z*y.z; acc.w += x.w*y.w;
    }
    acc.x *= (1.f/NH); acc.y *= (1.f/NH); acc.z *= (1.f/NH); acc.w *= (1.f/NH);
    __shared__ float red[256];
    red[tid] = acc.x + acc.y + acc.z + acc.w;
    __syncthreads();
    for (int o = 128; o > 0; o >>= 1) {
        if (tid < o) red[tid] += red[tid + o];
        __syncthreads();
    }
    float sc = 1.f / (red[0] + 1e-5f);
    size_t o = (size_t)r2*(Lseq/2) + tid*2;
    g_htaH[o]   = pack_h2(acc.x*sc, acc.y*sc);
    g_htaH[o+1] = pack_h2(acc.z*sc, acc.w*sc);
}

// ---------------- K5: gather -> single fp16 X ----------------
__global__ void k_gather(const int* __restrict__ hts)
{
    int r2 = blockIdx.x;
    int b = r2 / Rht;
    int e0 = hts[(size_t)r2*2 + 0];
    int e1 = hts[(size_t)r2*2 + 1];
    const float* emb0 = g_ent_emb + ((size_t)(b*NE + e0))*HID;
    const float* emb1 = g_ent_emb + ((size_t)(b*NE + e1))*HID;
    const float* rel  = g_rel + (size_t)r2*HID;
    for (int u = threadIdx.x; u < HID; u += 256) {
        if (u < HID/2) {
            float2 v0 = *(const float2*)&emb0[2*u];
            g_XH[(size_t)r2*HID + u] = pack_h2(v0.x, v0.y);
            float2 v1 = *(const float2*)&emb1[2*u];
            g_XH[(size_t)(NROW + r2)*HID + u] = pack_h2(v1.x, v1.y);
        } else {
            float2 rv = *(const float2*)&rel[2*u - HID];
            uint32_t p = pack_h2(rv.x, rv.y);
            g_XH[(size_t)r2*HID + u] = p;
            g_XH[(size_t)(NROW + r2)*HID + u] = p;
        }
    }
}

// ---------------- split + transpose: [z][K][N] f32 -> [z][N][K/2] fp16x2 ----
__global__ void __launch_bounds__(256)
k_splitT(const float* __restrict__ in, uint32_t* __restrict__ outHi,
         int K, int N, long sIn, long sOut)
{
    __shared__ float s[128][65];
    in    += (size_t)blockIdx.z * sIn;
    outHi += (size_t)blockIdx.z * sOut;
    int k0 = blockIdx.x*128, n0 = blockIdx.y*64;
    int tid = threadIdx.x;
#pragma unroll
    for (int u = 0; u < 8; u++) {
        int idx = tid + u*256;
        int kk = idx >> 4;
        int cc = (idx & 15) * 4;
        float4 v = *(const float4*)&in[(size_t)(k0+kk)*N + n0 + cc];
        s[kk][cc+0] = v.x; s[kk][cc+1] = v.y;
        s[kk][cc+2] = v.z; s[kk][cc+3] = v.w;
    }
    __syncthreads();
    int K2 = K >> 1;
#pragma unroll
    for (int u = 0; u < 4; u++) {
        int idx = tid + u*256;
        int nn = idx >> 4, q = idx & 15;
        uint32_t hi[4];
#pragma unroll
        for (int i = 0; i < 4; i++)
            hi[i] = pack_h2(s[q*8 + i*2][nn], s[q*8 + i*2 + 1][nn]);
        size_t o = (size_t)(n0+nn)*K2 + (k0 >> 1) + q*4;
        *(uint4*)&outHi[o] = make_uint4(hi[0], hi[1], hi[2], hi[3]);
    }
}

__global__ void k_bias2(const float* __restrict__ b0, const float* __restrict__ b1)
{
    int i = threadIdx.x + blockIdx.x*256;
    if (i < EMB) { g_bias_ht[i] = b0[i]; g_bias_ht[EMB+i] = b1[i]; }
}

// ---------------- 1-pass fp16 mma GEMM, templated N-tile (round-10) -------
template<int ACT, int NT>
__global__ void __launch_bounds__(256, 1)
k_gemm_h(const uint32_t* __restrict__ Ah, const uint32_t* __restrict__ Bh,
         const float* __restrict__ bias, float* __restrict__ C,
         int K, int N, long sA, long sB, long sC)
{
    constexpr int NFR  = NT/16;
    constexpr int BUFB = 16384 + NT*128;
    extern __shared__ char smem[];
    uint32_t sb = smem_u32(smem);
    int tid = threadIdx.x, lid = tid & 31, wid = tid >> 5;
    int row0 = blockIdx.y*128, col0 = blockIdx.x*NT;
    Ah += (size_t)blockIdx.z * sA;
    Bh += (size_t)blockIdx.z * sB;
    C  += (size_t)blockIdx.z * sC;
    const float* bz = bias ? bias + (size_t)blockIdx.z * N : nullptr;
    int K2 = K >> 1, nchunk = K >> 6;
    int wm = (wid >> 1)*32, wn = (wid & 1)*(NT/2);
    int msel = lid >> 3, r8 = lid & 7;

    float acc[2][NFR][4];
#pragma unroll
    for (int i = 0; i < 2; i++)
#pragma unroll
        for (int n = 0; n < NFR; n++)
#pragma unroll
            for (int q = 0; q < 4; q++) acc[i][n][q] = 0.f;

#define GLOADH(c) { \
    uint32_t base = sb + (uint32_t)((c)&1)*BUFB; \
    _Pragma("unroll") \
    for (int p = 0; p < 4; p++) { \
        int idx = tid + p*256; int r = idx >> 3, seg = idx & 7; \
        size_t goA = (size_t)(row0+r)*K2 + (size_t)(c)*32 + seg*4; \
        CPA16(base + SWZ((uint32_t)(r*128 + seg*16)), Ah + goA); \
    } \
    _Pragma("unroll") \
    for (int p = 0; p < NT/32; p++) { \
        int idx = tid + p*256; int r = idx >> 3, seg = idx & 7; \
        size_t goB = (size_t)(col0+r)*K2 + (size_t)(c)*32 + seg*4; \
        CPA16(base + 16384u + SWZ((uint32_t)(r*128 + seg*16)), Bh + goB); \
    } }

    GLOADH(0);
    asm volatile("cp.async.commit_group;");

#pragma unroll 1
    for (int c = 0; c < nchunk; ++c) {
        if (c + 1 < nchunk) GLOADH(c + 1);
        asm volatile("cp.async.commit_group;");
        asm volatile("cp.async.wait_group 1;");
        __syncthreads();

        uint32_t abase = sb + (uint32_t)(c & 1)*BUFB;
        uint32_t bbase = abase + 16384u;
#pragma unroll
        for (int s = 0; s < 4; ++s) {
            uint32_t ah[2][4];
#pragma unroll
            for (int i = 0; i < 2; ++i) {
                uint32_t off = SWZ((uint32_t)((wm + i*16 + (lid & 15))*128
                                              + s*32 + (lid >> 4)*16));
                LDX4(ah[i], abase + off);
            }
            uint32_t bh[2*NFR];
#pragma unroll
            for (int pq = 0; pq < NT/32; ++pq) {
                uint32_t off = SWZ((uint32_t)((wn + (pq*2 + (msel >> 1))*8 + r8)*128
                                              + s*32 + (msel & 1)*16));
                LDX4(&bh[pq*4], bbase + off);
            }
#pragma unroll
            for (int i = 0; i < 2; ++i)
#pragma unroll
                for (int n = 0; n < NFR; ++n)
                    MMA16816H(acc[i][n], ah[i][0],ah[i][1],ah[i][2],ah[i][3], bh[n*2], bh[n*2+1]);
        }
        __syncthreads();
    }
#undef GLOADH

#pragma unroll
    for (int i = 0; i < 2; ++i) {
        int gr = row0 + wm + i*16 + (lid >> 2);
#pragma unroll
        for (int n = 0; n < NFR; ++n) {
            int gc = col0 + wn + n*8 + (lid & 3)*2;
            float b0v = bz ? bz[gc] : 0.f, b1v = bz ? bz[gc+1] : 0.f;
            float v0 = acc[i][n][0] + b0v, v1 = acc[i][n][1] + b1v;
            float v2 = acc[i][n][2] + b0v, v3 = acc[i][n][3] + b1v;
            if (ACT == 1) { v0 = tanhf(v0); v1 = tanhf(v1); v2 = tanhf(v2); v3 = tanhf(v3); }
            *(float2*)&C[(size_t)gr*N + gc]     = make_float2(v0, v1);
            *(float2*)&C[(size_t)(gr+8)*N + gc] = make_float2(v2, v3);
        }
    }
}

// ---------------- fp32 SIMT sgemm (small tails: cls/proj) ----------------
template<int BM, int BN, int BK, int TM, int TN, int ACT>
__global__ __launch_bounds__((BM/TM)*(BN/TN))
void sgemm(const float* __restrict__ A, const float* __restrict__ B,
           const float* __restrict__ bias, float* __restrict__ C,
           int M, int N, int K)
{
    constexpr int THREADS = (BM/TM)*(BN/TN);
    __shared__ float As[BK][BM + 4];
    __shared__ float Bs[BK][BN];
    int tid = threadIdx.x;
    int tx = tid % (BN/TN);
    int ty = tid / (BN/TN);
    int row0 = blockIdx.y * BM, col0 = blockIdx.x * BN;
    float acc[TM][TN] = {};
    constexpr int AE = BM*BK/THREADS;
    constexpr int BE = BK*BN/THREADS;

    for (int k0 = 0; k0 < K; k0 += BK) {
#pragma unroll
        for (int u = 0; u < AE; u++) {
            int idx = tid + u*THREADS;
            int r = idx / BK, c = idx % BK;
            float v = 0.f;
            int gr = row0 + r;
            if (gr < M) v = A[(size_t)gr*K + k0 + c];
            As[c][r] = v;
        }
#pragma unroll
        for (int u = 0; u < BE; u++) {
            int idx = tid + u*THREADS;
            int r = idx / BN, c = idx % BN;
            float v = 0.f;
            int gc = col0 + c;
            if (gc < N) v = B[(size_t)(k0 + r)*N + gc];
            Bs[r][c] = v;
        }
        __syncthreads();
#pragma unroll
        for (int kk = 0; kk < BK; kk++) {
            float af[TM], bf[TN];
#pragma unroll
            for (int i = 0; i < TM; i += 4)
                *reinterpret_cast<float4*>(&af[i]) =
                    *reinterpret_cast<const float4*>(&As[kk][ty*TM + i]);
#pragma unroll
            for (int j = 0; j < TN; j += 4)
                *reinterpret_cast<float4*>(&bf[j]) =
                    *reinterpret_cast<const float4*>(&Bs[kk][tx*TN + j]);
#pragma unroll
            for (int i = 0; i < TM; i++)
#pragma unroll
                for (int j = 0; j < TN; j++)
                    acc[i][j] += af[i] * bf[j];
        }
        __syncthreads();
    }
#pragma unroll
    for (int i = 0; i < TM; i++) {
        int gr = row0 + ty*TM + i;
        if (gr >= M) continue;
#pragma unroll
        for (int j = 0; j < TN; j++) {
            int gc = col0 + tx*TN + j;
            if (gc >= N) continue;
            float v = acc[i][j];
            if (bias) v += bias[gc];
            if (ACT == 1) v = tanhf(v);
            C[(size_t)gr*N + gc] = v;
        }
    }
}

// ---------------- bilinear GEMM via fp16 mma ----------
// Round-15 structure + tt hoisted into 32 uint32 registers per j-block
// (round-14 retry at half the register cost). Inner loop: zero t-LDS.
#define BIL_BUF   24576u                    // per stage: 2 chunks x 12KB
#define BIL_SH_OFF (3*24576)
#define BIL_ST_OFF (3*24576 + 34816)        // s_t: uint32[128][36] = 18432 B
#define BIL_SMEM   (3*24576 + 34816 + 18432)  // 126976

__device__ __forceinline__ void bil_load2(uint32_t sb, int it, int col0, int tid)
{
    uint32_t dH = sb + (uint32_t)(it % 3)*BIL_BUF;
#pragma unroll
    for (int half = 0; half < 2; ++half) {
        int c = it*2 + half;
#pragma unroll
        for (int p = 0; p < 3; p++) {
            int idx = tid + p*256;
            int n = idx >> 3, seg = idx & 7;
            size_t go = (size_t)(col0 + n)*(KBIL/2) + (size_t)c*32 + seg*4;
            CPA16(dH + half*12288u + SWZ((uint32_t)(n*128 + seg*16)), g_WbilHi + go);
        }
    }
}

__global__ void __launch_bounds__(256, 1)
k_bilinear_mma(const float* __restrict__ h, const float* __restrict__ t,
               const float* __restrict__ bias, float* __restrict__ out)
{
    extern __shared__ char smem[];
    uint32_t sb = smem_u32(smem);
    float* s_h = (float*)(smem + BIL_SH_OFF);        // [128][68] fp32
    uint32_t* s_t = (uint32_t*)(smem + BIL_ST_OFF);  // [128][36] fp16x2
    int tid = threadIdx.x, lid = tid & 31, wid = tid >> 5;
    int row0 = blockIdx.y * 128, col0 = blockIdx.x * 96;
    int wm = (wid >> 1) * 32;
    int wn = (wid & 1) * 48;
    int msel = lid >> 3, r8 = lid & 7;

    float acc[2][6][4];
#pragma unroll
    for (int i = 0; i < 2; i++)
#pragma unroll
        for (int n = 0; n < 6; n++)
#pragma unroll
            for (int q = 0; q < 4; q++) acc[i][n][q] = 0.f;

    uint32_t tt[4][2][4];   // [s][i][ta,tb,tc,td] fp16x2 — 32 regs/j-block

    // prologue: stages 0 and 1 in flight
    bil_load2(sb, 0, col0, tid);
    asm volatile("cp.async.commit_group;");
    bil_load2(sb, 1, col0, tid);
    asm volatile("cp.async.commit_group;");

#pragma unroll 1
    for (int it = 0; it < NITER; ++it) {
        asm volatile("cp.async.wait_group 1;");   // stage `it` ready
        __syncthreads();                          // all warps past it-1 compute

        if ((it & 31) == 0) {                     // new j-block
            int j = it >> 5;
            for (int idx = tid; idx < 128*16; idx += 256) {
                int rr = idx >> 4, cc = (idx & 15) * 4;
                *(float4*)&s_h[rr*68 + cc] =
                    *(const float4*)&h[(size_t)(row0+rr)*EMB + j*64 + cc];
                float4 tv = *(const float4*)&t[(size_t)(row0+rr)*EMB + j*64 + cc];
                s_t[rr*36 + (cc >> 1)]     = pack_h2(tv.x, tv.y);
                s_t[rr*36 + (cc >> 1) + 1] = pack_h2(tv.z, tv.w);
            }
            __syncthreads();
            // hoist t fragments (fp16x2) for the entire j-block
#pragma unroll
            for (int s = 0; s < 4; ++s)
#pragma unroll
                for (int i = 0; i < 2; ++i) {
                    int rb = (wm + i*16 + (lid >> 2))*36;
                    int cq = s*8 + (lid & 3);
                    tt[s][i][0] = s_t[rb + cq];
                    tt[s][i][1] = s_t[rb + cq + 4];
                    tt[s][i][2] = s_t[rb + 8*36 + cq];
                    tt[s][i][3] = s_t[rb + 8*36 + cq + 4];
                }
        }

        uint32_t stage = sb + (uint32_t)(it % 3)*BIL_BUF;
        int a0c = (it*2)     & 63;
        int a1c = (it*2 + 1) & 63;
        uint32_t hd[2][2][2];   // [half][hi-lo row][i]
#pragma unroll
        for (int i = 0; i < 2; i++) {
            int r0 = wm + i*16 + (lid >> 2);
            float v;
            v = s_h[r0*68 + a0c];       hd[0][0][i] = pack_h2(v, v);
            v = s_h[(r0 + 8)*68 + a0c]; hd[0][1][i] = pack_h2(v, v);
            v = s_h[r0*68 + a1c];       hd[1][0][i] = pack_h2(v, v);
            v = s_h[(r0 + 8)*68 + a1c]; hd[1][1][i] = pack_h2(v, v);
        }

#pragma unroll
        for (int s = 0; s < 4; ++s) {
#pragma unroll
            for (int half = 0; half < 2; ++half) {
                uint32_t bbase = stage + half*12288u;
                uint32_t bh[12];
#pragma unroll
                for (int pq = 0; pq < 3; ++pq) {
                    uint32_t off = SWZ((uint32_t)((wn + (pq*2 + (msel >> 1))*8 + r8)*128
                                                  + s*32 + (msel & 1)*16));
                    LDX4(&bh[pq*4], bbase + off);
                }
#pragma unroll
                for (int i = 0; i < 2; ++i) {
                    uint32_t ah[4];
                    ah[0] = hmul2(hd[half][0][i], tt[s][i][0]);
                    ah[1] = hmul2(hd[half][1][i], tt[s][i][2]);
                    ah[2] = hmul2(hd[half][0][i], tt[s][i][1]);
                    ah[3] = hmul2(hd[half][1][i], tt[s][i][3]);
#pragma unroll
                    for (int n = 0; n < 6; ++n)
                        MMA16816H(acc[i][n], ah[0],ah[1],ah[2],ah[3], bh[n*2], bh[n*2+1]);
                }
            }
        }

        // issue stage it+2 AFTER compute (proven faster position)
        if (it + 2 < NITER) bil_load2(sb, it + 2, col0, tid);
        asm volatile("cp.async.commit_group;");
    }

#pragma unroll
    for (int i = 0; i < 2; ++i) {
        int gr = row0 + wm + i*16 + (lid >> 2);
#pragma unroll
        for (int n = 0; n < 6; ++n) {
            int gc = col0 + wn + n*8 + (lid & 3)*2;
            float2 v0 = make_float2(acc[i][n][0] + bias[gc],
                                    acc[i][n][1] + bias[gc+1]);
            float2 v1 = make_float2(acc[i][n][2] + bias[gc],
                                    acc[i][n][3] + bias[gc+1]);
            *(float2*)&out[(size_t)gr*EMB + gc]     = v0;
            *(float2*)&out[(size_t)(gr+8)*EMB + gc] = v1;
        }
    }
}

// ---------------- launch ----------------
extern "C" void kernel_launch(void* const* d_in, const int* in_sizes, int n_in,
                              void* d_out, int out_size)
{
    const float* seq    = (const float*)d_in[0];
    const float* ent    = (const float*)d_in[1];
    const float* attn   = (const float*)d_in[2];
    const int*   labels = (const int*)  d_in[3];
    const int*   hts    = (const int*)  d_in[4];
    const float* W_head = (const float*)d_in[5];
    const float* b_head = (const float*)d_in[6];
    const float* W_tail = (const float*)d_in[7];
    const float* b_tail = (const float*)d_in[8];
    const float* W_bil  = (const float*)d_in[9];
    const float* b_bil  = (const float*)d_in[10];
    const float* W_cls  = (const float*)d_in[11];
    const float* b_cls  = (const float*)d_in[12];
    const float* W_proj = (const float*)d_in[13];
    const float* b_proj = (const float*)d_in[14];

    float* out      = (float*)d_out;
    float* out_cls  = out + (size_t)NROW*EMB;
    float* out_proj = out_cls + (size_t)NROW*NCLS;

    void *p_rel, *p_ht, *p_biasht;
    void *p_WbHi, *p_WhtHi, *p_seqHi, *p_htaH, *p_XH;
    cudaGetSymbolAddress(&p_rel,   g_rel);
    cudaGetSymbolAddress(&p_ht,    g_ht);
    cudaGetSymbolAddress(&p_biasht,g_bias_ht);
    cudaGetSymbolAddress(&p_WbHi,  g_WbilHi);
    cudaGetSymbolAddress(&p_WhtHi, g_WhtHi);
    cudaGetSymbolAddress(&p_seqHi, g_seqTHi);
    cudaGetSymbolAddress(&p_htaH,  g_htaH);
    cudaGetSymbolAddress(&p_XH,    g_XH);

    cudaFuncSetAttribute(k_bilinear_mma,
                         cudaFuncAttributeMaxDynamicSharedMemorySize, BIL_SMEM);
    cudaFuncSetAttribute(k_gemm_h<0,128>,
                         cudaFuncAttributeMaxDynamicSharedMemorySize, 65536);
    cudaFuncSetAttribute(k_gemm_h<1,64>,
                         cudaFuncAttributeMaxDynamicSharedMemorySize, 49152);

    static cudaStream_t s1 = nullptr, s2 = nullptr;
    static cudaEvent_t evFork = nullptr, evSeq = nullptr, evJoin = nullptr,
                       evEnt = nullptr, evBil = nullptr, evProj = nullptr;
    if (!s1) {
        cudaStreamCreateWithFlags(&s1, cudaStreamNonBlocking);
        cudaStreamCreateWithFlags(&s2, cudaStreamNonBlocking);
        cudaEventCreateWithFlags(&evFork, cudaEventDisableTiming);
        cudaEventCreateWithFlags(&evSeq,  cudaEventDisableTiming);
        cudaEventCreateWithFlags(&evJoin, cudaEventDisableTiming);
        cudaEventCreateWithFlags(&evEnt,  cudaEventDisableTiming);
        cudaEventCreateWithFlags(&evBil,  cudaEventDisableTiming);
        cudaEventCreateWithFlags(&evProj, cudaEventDisableTiming);
    }

    cudaEventRecord(evFork, 0);
    cudaStreamWaitEvent(s1, evFork, 0);
    cudaStreamWaitEvent(s2, evFork, 0);

    // ---- s2: entity pooling (independent of attn path) ----
    k_ent_emb<<<dim3(NE, Bdoc), 256, 0, s2>>>(ent, labels);
    cudaEventRecord(evEnt, s2);

    // ---- s1: seq split (needed by rel), then weight splits ----
    k_splitT<<<dim3(Lseq/128, HID/64, Bdoc), 256, 0, s1>>>(seq,
        (uint32_t*)p_seqHi, Lseq, HID, (long)Lseq*HID, (long)HID*(Lseq/2));
    cudaEventRecord(evSeq, s1);
    k_bias2<<<3, 256, 0, s1>>>(b_head, b_tail);
    k_splitT<<<dim3(2*HID/128, EMB/64), 256, 0, s1>>>(W_head,
        (uint32_t*)p_WhtHi, 2*HID, EMB, 0, 0);
    k_splitT<<<dim3(2*HID/128, EMB/64), 256, 0, s1>>>(W_tail,
        (uint32_t*)p_WhtHi + (size_t)EMB*HID, 2*HID, EMB, 0, 0);
    k_splitT<<<dim3(KBIL/128, EMB/64), 256, 0, s1>>>(W_bil,
        (uint32_t*)p_WbHi, KBIL, EMB, 0, 0);
    cudaEventRecord(evJoin, s1);

    // ---- main: attention pooling chain ----
    k_attn_mean<<<dim3(NE, NH, Bdoc), 256>>>(attn, labels);
    k_hta<<<dim3(Rht, Bdoc), 256>>>(hts);

    // rel = hta @ seq (1-pass fp16, N-tile 128)
    cudaStreamWaitEvent(0, evSeq, 0);
    k_gemm_h<0,128><<<dim3(HID/128, Rht/128, Bdoc), 256, 65536>>>(
        (const uint32_t*)p_htaH, (const uint32_t*)p_seqHi,
        nullptr, (float*)p_rel,
        Lseq, HID, (long)Rht*(Lseq/2), (long)HID*(Lseq/2), (long)Rht*HID);

    cudaStreamWaitEvent(0, evEnt, 0);
    k_gather<<<NROW, 256>>>(hts);

    cudaStreamWaitEvent(0, evJoin, 0);

    // h and t in one launch (z = head/tail), 1-pass fp16, N-tile 64
    k_gemm_h<1,64><<<dim3(EMB/64, NROW/128, 2), 256, 49152>>>(
        (const uint32_t*)p_XH, (const uint32_t*)p_WhtHi,
        (const float*)p_biasht, (float*)p_ht,
        2*HID, EMB, (long)NROW*HID, (long)EMB*HID, (long)NROW*EMB);

    // bilinear (fp16 1-pass) -> d_out (embeds)
    k_bilinear_mma<<<dim3(EMB/96, NROW/128), 256, BIL_SMEM>>>(
        (const float*)p_ht, (const float*)p_ht + (size_t)NROW*EMB, b_bil, out);
    cudaEventRecord(evBil, 0);

    // proj on s1 (concurrent with cls)
    cudaStreamWaitEvent(s1, evBil, 0);
    sgemm<64,32,16,4,4,1><<<dim3(NPROJ/32, NROW/64), 128, 0, s1>>>(
        out, W_proj, b_proj, out_proj, NROW, NPROJ, EMB);
    cudaEventRecord(evProj, s1);

    // cls on main
    sgemm<64,32,16,4,4,0><<<dim3((NCLS+31)/32, NROW/64), 128>>>(
        out, W_cls, b_cls, out_cls, NROW, NCLS, EMB);
    cudaStreamWaitEvent(0, evProj, 0);
}